// round 1
// baseline (speedup 1.0000x reference)
#include <cuda_runtime.h>
#include <cuda_bf16.h>

#define CH   256
#define IMG  128
#define HW   (IMG*IMG)        // 16384
#define BATCH 4
#define HEADS 4
#define D    64
#define BLK  8
#define HALO 3
#define WIN  14                // BLK + 2*HALO
#define NB   16                // IMG/BLK
#define NPOS 64                // BLK*BLK
#define NWIN 196               // WIN*WIN

// Scratch (allocation-free rule: __device__ globals)
__device__ float g_naux[(long)BATCH*CH*HW];
__device__ float g_q   [(long)BATCH*CH*HW];
__device__ float g_k   [(long)BATCH*CH*HW];
__device__ float g_v   [(long)BATCH*CH*HW];

// ---------------------------------------------------------------------------
// Conv1x1 as GEMM: C[o,p] = f( sum_c A[o,c] * B[c,p] )
// A: M x K row-major (weights). B rows 0..K0-1 from B0, K0..K-1 from B1.
// ldb = ldc = HW, per-batch stride CH*HW on B and C. M=256, N=16384/batch.
// mode 0: relu(x + bias[o]); mode 1: x*scale; mode 2: x
// ---------------------------------------------------------------------------
__global__ __launch_bounds__(256)
void gemm_conv(const float* __restrict__ A,
               const float* __restrict__ B0,
               const float* __restrict__ B1,
               int K, int K0,
               float* __restrict__ C,
               const float* __restrict__ bias,
               float scale, int mode)
{
    const int tid = threadIdx.x;
    const int b   = blockIdx.z;
    const int n0  = blockIdx.x * 128;
    const int m0  = blockIdx.y * 128;
    const long boff = (long)b * CH * HW;
    const float* Bb0 = B0 + boff;
    const float* Bb1 = B1 ? (B1 + boff) : nullptr;
    float* Cb = C + boff;

    __shared__ float As[16][132];   // padded (stores are transposed)
    __shared__ float Bs[16][128];

    const int ty8 = (tid >> 4) * 8;   // 0..120
    const int tx8 = (tid & 15) * 8;   // 0..120

    float acc[8][8];
#pragma unroll
    for (int i = 0; i < 8; i++)
#pragma unroll
        for (int j = 0; j < 8; j++) acc[i][j] = 0.f;

    for (int k0 = 0; k0 < K; k0 += 16) {
        // Load A tile (128 x 16), transpose into As[k][m]
#pragma unroll
        for (int p = 0; p < 2; p++) {
            int row = p * 64 + (tid >> 2);
            int col = (tid & 3) * 4;
            float4 av = *(const float4*)&A[(long)(m0 + row) * K + k0 + col];
            As[col + 0][row] = av.x;
            As[col + 1][row] = av.y;
            As[col + 2][row] = av.z;
            As[col + 3][row] = av.w;
        }
        // Load B tile (16 x 128)
#pragma unroll
        for (int p = 0; p < 2; p++) {
            int row = p * 8 + (tid >> 5);
            int col = (tid & 31) * 4;
            int kr = k0 + row;
            const float* src = (kr < K0) ? (Bb0 + (long)kr * HW)
                                         : (Bb1 + (long)(kr - K0) * HW);
            *(float4*)&Bs[row][col] = *(const float4*)&src[n0 + col];
        }
        __syncthreads();

#pragma unroll
        for (int kk = 0; kk < 16; kk++) {
            float a[8], bb[8];
#pragma unroll
            for (int i = 0; i < 8; i++) a[i] = As[kk][ty8 + i];
#pragma unroll
            for (int j = 0; j < 8; j++) bb[j] = Bs[kk][tx8 + j];
#pragma unroll
            for (int i = 0; i < 8; i++)
#pragma unroll
                for (int j = 0; j < 8; j++) acc[i][j] = fmaf(a[i], bb[j], acc[i][j]);
        }
        __syncthreads();
    }

    // Epilogue
#pragma unroll
    for (int i = 0; i < 8; i++) {
        int o = m0 + ty8 + i;
        float bi = (mode == 0) ? bias[o] : 0.f;
        float* dst = &Cb[(long)o * HW + n0 + tx8];
#pragma unroll
        for (int j = 0; j < 8; j++) {
            float v = acc[i][j];
            if (mode == 0)      v = fmaxf(v + bi, 0.f);
            else if (mode == 1) v = v * scale;
            dst[j] = v;
        }
    }
}

// ---------------------------------------------------------------------------
// Halo attention: one CTA per (b, by*16+bx, head).
// Q: 64 pos x 64 ch. K,V windows: 196 pos x 64 ch.
// K padded-with-zero THEN rel bias added (so OOB K = bias only); V zero-padded.
// ---------------------------------------------------------------------------
#define QSTR 65
#define KSTR 65
#define SSTR 197
#define SMEM_FLOATS (NPOS*QSTR + NWIN*KSTR + NPOS*SSTR)

__global__ __launch_bounds__(256)
void attn_kernel(const float* __restrict__ gq, const float* __restrict__ gk,
                 const float* __restrict__ gv, const float* __restrict__ relh,
                 const float* __restrict__ relw, float* __restrict__ out)
{
    extern __shared__ float sm[];
    float* Qs  = sm;                       // [64][QSTR]
    float* KV  = sm + NPOS * QSTR;         // [196][KSTR]
    float* SIM = KV + NWIN * KSTR;         // [64][SSTR]

    const int tid = threadIdx.x;
    const int blk = blockIdx.x;            // by*16 + bx
    const int h   = blockIdx.y;
    const int b   = blockIdx.z;
    const int by  = blk >> 4, bx = blk & 15;
    const int y0  = by * BLK, x0 = bx * BLK;
    const long base = ((long)b * CH + h * D) * HW;

    // Load Q tile
    for (int idx = tid; idx < NPOS * D; idx += 256) {
        int c = idx >> 6, pos = idx & 63;
        int y = y0 + (pos >> 3), x = x0 + (pos & 7);
        Qs[pos * QSTR + c] = gq[base + (long)c * HW + y * IMG + x];
    }
    // Load K window + rel bias
    for (int idx = tid; idx < NWIN * D; idx += 256) {
        int c = idx / NWIN, j = idx % NWIN;
        int iw = j / WIN, jw = j % WIN;
        int y = y0 - HALO + iw, x = x0 - HALO + jw;
        float v = 0.f;
        if (y >= 0 && y < IMG && x >= 0 && x < IMG)
            v = gk[base + (long)c * HW + y * IMG + x];
        v += (c < 32) ? relh[iw * 32 + c] : relw[jw * 32 + (c - 32)];
        KV[j * KSTR + c] = v;
    }
    __syncthreads();

    // sim[64][196] = Q @ K^T
    {
        const int ty = tid >> 4, tx = tid & 15;
        float acc[4][13];
#pragma unroll
        for (int ii = 0; ii < 4; ii++)
#pragma unroll
            for (int jj = 0; jj < 13; jj++) acc[ii][jj] = 0.f;

        for (int c = 0; c < D; c++) {
            float a[4];
#pragma unroll
            for (int ii = 0; ii < 4; ii++) a[ii] = Qs[(ty * 4 + ii) * QSTR + c];
#pragma unroll
            for (int jj = 0; jj < 13; jj++) {
                int j = jj * 16 + tx;
                float bv = (j < NWIN) ? KV[j * KSTR + c] : 0.f;
#pragma unroll
                for (int ii = 0; ii < 4; ii++)
                    acc[ii][jj] = fmaf(a[ii], bv, acc[ii][jj]);
            }
        }
#pragma unroll
        for (int ii = 0; ii < 4; ii++)
#pragma unroll
            for (int jj = 0; jj < 13; jj++) {
                int j = jj * 16 + tx;
                if (j < NWIN) SIM[(ty * 4 + ii) * SSTR + j] = acc[ii][jj];
            }
    }
    __syncthreads();

    // Softmax over j (groups of 4 threads per row)
    {
        int row = tid >> 2, l4 = tid & 3;
        float* r = &SIM[row * SSTR];
        float mx = -1e30f;
        for (int j = l4; j < NWIN; j += 4) mx = fmaxf(mx, r[j]);
        mx = fmaxf(mx, __shfl_xor_sync(0xffffffffu, mx, 1));
        mx = fmaxf(mx, __shfl_xor_sync(0xffffffffu, mx, 2));
        float s = 0.f;
        for (int j = l4; j < NWIN; j += 4) {
            float e = expf(r[j] - mx);
            r[j] = e;
            s += e;
        }
        s += __shfl_xor_sync(0xffffffffu, s, 1);
        s += __shfl_xor_sync(0xffffffffu, s, 2);
        float inv = 1.f / s;
        for (int j = l4; j < NWIN; j += 4) r[j] *= inv;
    }
    __syncthreads();

    // Load V window (zero-padded) into KV
    for (int idx = tid; idx < NWIN * D; idx += 256) {
        int c = idx / NWIN, j = idx % NWIN;
        int iw = j / WIN, jw = j % WIN;
        int y = y0 - HALO + iw, x = x0 - HALO + jw;
        float v = 0.f;
        if (y >= 0 && y < IMG && x >= 0 && x < IMG)
            v = gv[base + (long)c * HW + y * IMG + x];
        KV[j * KSTR + c] = v;
    }
    __syncthreads();

    // out[64][64] = attn @ V, write to (B,C,H,W)
    {
        const int ty = tid >> 4, tx = tid & 15;
        float acc[4][4];
#pragma unroll
        for (int ii = 0; ii < 4; ii++)
#pragma unroll
            for (int cc = 0; cc < 4; cc++) acc[ii][cc] = 0.f;

        for (int j = 0; j < NWIN; j++) {
            float a[4], bv[4];
#pragma unroll
            for (int ii = 0; ii < 4; ii++) a[ii] = SIM[(ty * 4 + ii) * SSTR + j];
#pragma unroll
            for (int cc = 0; cc < 4; cc++) bv[cc] = KV[j * KSTR + tx * 4 + cc];
#pragma unroll
            for (int ii = 0; ii < 4; ii++)
#pragma unroll
                for (int cc = 0; cc < 4; cc++)
                    acc[ii][cc] = fmaf(a[ii], bv[cc], acc[ii][cc]);
        }
#pragma unroll
        for (int ii = 0; ii < 4; ii++) {
            int i = ty * 4 + ii;
            int y = y0 + (i >> 3), x = x0 + (i & 7);
#pragma unroll
            for (int cc = 0; cc < 4; cc++) {
                int c = tx * 4 + cc;
                out[base + (long)c * HW + y * IMG + x] = acc[ii][cc];
            }
        }
    }
}

// ---------------------------------------------------------------------------
extern "C" void kernel_launch(void* const* d_in, const int* in_sizes, int n_in,
                              void* d_out, int out_size)
{
    const float* noisy = (const float*)d_in[0];
    const float* aux   = (const float*)d_in[1];
    const float* w_map = (const float*)d_in[2];
    const float* b_map = (const float*)d_in[3];
    const float* w_q   = (const float*)d_in[4];
    const float* w_k   = (const float*)d_in[5];
    const float* w_v   = (const float*)d_in[6];
    const float* rel_h = (const float*)d_in[7];
    const float* rel_w = (const float*)d_in[8];
    float* out = (float*)d_out;

    float *naux, *q, *k, *v;
    cudaGetSymbolAddress((void**)&naux, g_naux);
    cudaGetSymbolAddress((void**)&q,    g_q);
    cudaGetSymbolAddress((void**)&k,    g_k);
    cudaGetSymbolAddress((void**)&v,    g_v);

    dim3 ggrid(HW / 128, CH / 128, BATCH);   // (128, 2, 4)

    // n_aux = relu(Wmap @ [noisy; aux] + b)
    gemm_conv<<<ggrid, 256>>>(w_map, noisy, aux, 2 * CH, CH, naux, b_map, 1.f, 0);
    // q = 0.125 * (Wq @ n_aux)
    gemm_conv<<<ggrid, 256>>>(w_q, naux, nullptr, CH, CH, q, nullptr, 0.125f, 1);
    // k = Wk @ n_aux
    gemm_conv<<<ggrid, 256>>>(w_k, naux, nullptr, CH, CH, k, nullptr, 1.f, 2);
    // v = Wv @ noisy
    gemm_conv<<<ggrid, 256>>>(w_v, noisy, nullptr, CH, CH, v, nullptr, 1.f, 2);

    // attention
    size_t smem = (size_t)SMEM_FLOATS * sizeof(float);   // ~118 KB
    cudaFuncSetAttribute(attn_kernel,
                         cudaFuncAttributeMaxDynamicSharedMemorySize, (int)smem);
    attn_kernel<<<dim3(NB * NB, HEADS, BATCH), 256, smem>>>(q, k, v, rel_h, rel_w, out);
}

// round 2
// speedup vs baseline: 1.2729x; 1.2729x over previous
#include <cuda_runtime.h>
#include <cuda_bf16.h>

#define CH   256
#define IMG  128
#define HW   (IMG*IMG)        // 16384
#define BATCH 4
#define HEADS 4
#define D    64
#define BLK  8
#define HALO 3
#define WIN  14                // BLK + 2*HALO
#define NB   16                // IMG/BLK
#define NPOS 64                // BLK*BLK
#define NWIN 196               // WIN*WIN

// Scratch (allocation-free rule: __device__ globals)
__device__ float g_naux[(long)BATCH*CH*HW];
__device__ float g_q   [(long)BATCH*CH*HW];
__device__ float g_k   [(long)BATCH*CH*HW];
__device__ float g_v   [(long)BATCH*CH*HW];

// ---------------------------------------------------------------------------
// Conv1x1 as GEMM (unchanged from R0 — at fp32 roofline)
// ---------------------------------------------------------------------------
__global__ __launch_bounds__(256)
void gemm_conv(const float* __restrict__ A,
               const float* __restrict__ B0,
               const float* __restrict__ B1,
               int K, int K0,
               float* __restrict__ C,
               const float* __restrict__ bias,
               float scale, int mode)
{
    const int tid = threadIdx.x;
    const int b   = blockIdx.z;
    const int n0  = blockIdx.x * 128;
    const int m0  = blockIdx.y * 128;
    const long boff = (long)b * CH * HW;
    const float* Bb0 = B0 + boff;
    const float* Bb1 = B1 ? (B1 + boff) : nullptr;
    float* Cb = C + boff;

    __shared__ float As[16][132];
    __shared__ float Bs[16][128];

    const int ty8 = (tid >> 4) * 8;
    const int tx8 = (tid & 15) * 8;

    float acc[8][8];
#pragma unroll
    for (int i = 0; i < 8; i++)
#pragma unroll
        for (int j = 0; j < 8; j++) acc[i][j] = 0.f;

    for (int k0 = 0; k0 < K; k0 += 16) {
#pragma unroll
        for (int p = 0; p < 2; p++) {
            int row = p * 64 + (tid >> 2);
            int col = (tid & 3) * 4;
            float4 av = *(const float4*)&A[(long)(m0 + row) * K + k0 + col];
            As[col + 0][row] = av.x;
            As[col + 1][row] = av.y;
            As[col + 2][row] = av.z;
            As[col + 3][row] = av.w;
        }
#pragma unroll
        for (int p = 0; p < 2; p++) {
            int row = p * 8 + (tid >> 5);
            int col = (tid & 31) * 4;
            int kr = k0 + row;
            const float* src = (kr < K0) ? (Bb0 + (long)kr * HW)
                                         : (Bb1 + (long)(kr - K0) * HW);
            *(float4*)&Bs[row][col] = *(const float4*)&src[n0 + col];
        }
        __syncthreads();

#pragma unroll
        for (int kk = 0; kk < 16; kk++) {
            float a[8], bb[8];
#pragma unroll
            for (int i = 0; i < 8; i++) a[i] = As[kk][ty8 + i];
#pragma unroll
            for (int j = 0; j < 8; j++) bb[j] = Bs[kk][tx8 + j];
#pragma unroll
            for (int i = 0; i < 8; i++)
#pragma unroll
                for (int j = 0; j < 8; j++) acc[i][j] = fmaf(a[i], bb[j], acc[i][j]);
        }
        __syncthreads();
    }

#pragma unroll
    for (int i = 0; i < 8; i++) {
        int o = m0 + ty8 + i;
        float bi = (mode == 0) ? bias[o] : 0.f;
        float* dst = &Cb[(long)o * HW + n0 + tx8];
#pragma unroll
        for (int j = 0; j < 8; j++) {
            float v = acc[i][j];
            if (mode == 0)      v = fmaxf(v + bi, 0.f);
            else if (mode == 1) v = v * scale;
            dst[j] = v;
        }
    }
}

// ---------------------------------------------------------------------------
// Halo attention v2: channel-major operands, simT layout, vectorized LDS,
// buffer overlay to fit 2 CTAs/SM (103.6 KB dynamic smem).
//
// smem float offsets:
//   phase 1-2:  Qc  [64c][64i]         @ 0      (4096)
//               Kc  [64c][200j]        @ 4096   (12800)   (j 196..199 = 0)
//   phase 3+ :  SIMT[200j][64i]        @ 0      (12800)   (overlays Qc,Kc head)
//               Vr  [196j][stride 68]  @ 12800  (13328)   (overlays Kc tail)
//   red [4][64] @ 26128, mx[64] @ 26384, inv_s[64] @ 26448  -> total 26512
// ---------------------------------------------------------------------------
#define SM_QC    0
#define SM_KC    4096
#define SM_SIMT  0
#define SM_VR    12800
#define VR_STR   68
#define SM_RED   26128
#define SM_MX    26384
#define SM_INV   26448
#define SM_TOT   26512

__global__ __launch_bounds__(256, 2)
void attn_kernel(const float* __restrict__ gq, const float* __restrict__ gk,
                 const float* __restrict__ gv, const float* __restrict__ relh,
                 const float* __restrict__ relw, float* __restrict__ out)
{
    extern __shared__ float sm[];
    const int tid = threadIdx.x;
    const int blk = blockIdx.x;
    const int h   = blockIdx.y;
    const int b   = blockIdx.z;
    const int by  = blk >> 4, bx = blk & 15;
    const int y0  = by * BLK, x0 = bx * BLK;
    const long base = ((long)b * CH + h * D) * HW;

    // ---- phase 1: load Qc (c-major) and Kc (c-major, +rel bias, zero pad) ----
    for (int idx = tid; idx < NPOS * D; idx += 256) {
        int c = idx >> 6, pos = idx & 63;
        int y = y0 + (pos >> 3), x = x0 + (pos & 7);
        sm[SM_QC + c * 64 + pos] = gq[base + (long)c * HW + y * IMG + x];
    }
    for (int idx = tid; idx < D * 200; idx += 256) {
        int c = idx / 200, j = idx - c * 200;
        float v = 0.f;
        if (j < NWIN) {
            int iw = j / WIN, jw = j - iw * WIN;
            int y = y0 - HALO + iw, x = x0 - HALO + jw;
            if (y >= 0 && y < IMG && x >= 0 && x < IMG)
                v = gk[base + (long)c * HW + y * IMG + x];
            v += (c < 32) ? relh[iw * 32 + c] : relw[jw * 32 + (c - 32)];
        }
        sm[SM_KC + idx] = v;
    }
    __syncthreads();

    // ---- phase 2: simT[j][i] = sum_c K[j][c] * Q[i][c]  (8x8 reg tiles) ----
    float acc[8][8];
    int j0 = 0, i0 = 0;
    if (tid < 200) {
        j0 = (tid >> 3) * 8;       // 0..192
        i0 = (tid & 7) * 8;        // 0..56
#pragma unroll
        for (int a = 0; a < 8; a++)
#pragma unroll
            for (int bb2 = 0; bb2 < 8; bb2++) acc[a][bb2] = 0.f;

        for (int c = 0; c < D; c++) {
            float4 k0v = *(const float4*)&sm[SM_KC + c * 200 + j0];
            float4 k1v = *(const float4*)&sm[SM_KC + c * 200 + j0 + 4];
            float4 q0v = *(const float4*)&sm[SM_QC + c * 64 + i0];
            float4 q1v = *(const float4*)&sm[SM_QC + c * 64 + i0 + 4];
            float ka[8] = {k0v.x,k0v.y,k0v.z,k0v.w,k1v.x,k1v.y,k1v.z,k1v.w};
            float qa[8] = {q0v.x,q0v.y,q0v.z,q0v.w,q1v.x,q1v.y,q1v.z,q1v.w};
#pragma unroll
            for (int jj = 0; jj < 8; jj++)
#pragma unroll
                for (int ii = 0; ii < 8; ii++)
                    acc[jj][ii] = fmaf(ka[jj], qa[ii], acc[jj][ii]);
        }
    }
    __syncthreads();   // Qc/Kc dead; safe to overlay

    // ---- phase 3: write simT; load Vr (transposed store) ----
    if (tid < 200) {
#pragma unroll
        for (int jj = 0; jj < 8; jj++) {
            *(float4*)&sm[SM_SIMT + (j0 + jj) * 64 + i0]     =
                make_float4(acc[jj][0], acc[jj][1], acc[jj][2], acc[jj][3]);
            *(float4*)&sm[SM_SIMT + (j0 + jj) * 64 + i0 + 4] =
                make_float4(acc[jj][4], acc[jj][5], acc[jj][6], acc[jj][7]);
        }
    }
    for (int idx = tid; idx < D * NWIN; idx += 256) {
        int c = idx / NWIN, j = idx - c * NWIN;
        int iw = j / WIN, jw = j - iw * WIN;
        int y = y0 - HALO + iw, x = x0 - HALO + jw;
        float v = 0.f;
        if (y >= 0 && y < IMG && x >= 0 && x < IMG)
            v = gv[base + (long)c * HW + y * IMG + x];
        sm[SM_VR + j * VR_STR + c] = v;
    }
    __syncthreads();

    // ---- phase 4: softmax over j per column i (unnormalized exp; inv later) --
    {
        const int i = tid & 63, p = tid >> 6;     // 4 parts x 49 j each
        const int jb = p * 49;
        float m = -1e30f;
#pragma unroll 7
        for (int jj = 0; jj < 49; jj++)
            m = fmaxf(m, sm[SM_SIMT + (jb + jj) * 64 + i]);
        sm[SM_RED + p * 64 + i] = m;
        __syncthreads();
        if (tid < 64) {
            float mm = fmaxf(fmaxf(sm[SM_RED + tid], sm[SM_RED + 64 + tid]),
                             fmaxf(sm[SM_RED + 128 + tid], sm[SM_RED + 192 + tid]));
            sm[SM_MX + tid] = mm;
        }
        __syncthreads();
        float mm = sm[SM_MX + i];
        float s = 0.f;
#pragma unroll 7
        for (int jj = 0; jj < 49; jj++) {
            float e = __expf(sm[SM_SIMT + (jb + jj) * 64 + i] - mm);
            sm[SM_SIMT + (jb + jj) * 64 + i] = e;
            s += e;
        }
        sm[SM_RED + p * 64 + i] = s;
        __syncthreads();
        if (tid < 64) {
            float ss = sm[SM_RED + tid] + sm[SM_RED + 64 + tid]
                     + sm[SM_RED + 128 + tid] + sm[SM_RED + 192 + tid];
            sm[SM_INV + tid] = 1.f / ss;
        }
        __syncthreads();
    }

    // ---- phase 5: out[i][c] = (sum_j e[j][i] * V[j][c]) * inv_s[i] ----------
    {
        const int it = tid >> 4, ct = tid & 15;   // 16x16 grid, 4x4 tiles
        const int oi0 = it * 4, oc0 = ct * 4;
        float acc2[4][4];
#pragma unroll
        for (int a = 0; a < 4; a++)
#pragma unroll
            for (int bb2 = 0; bb2 < 4; bb2++) acc2[a][bb2] = 0.f;

#pragma unroll 4
        for (int j = 0; j < NWIN; j++) {
            float4 av = *(const float4*)&sm[SM_SIMT + j * 64 + oi0];
            float4 bv = *(const float4*)&sm[SM_VR + j * VR_STR + oc0];
            float aa[4] = {av.x, av.y, av.z, av.w};
            float vv[4] = {bv.x, bv.y, bv.z, bv.w};
#pragma unroll
            for (int ii = 0; ii < 4; ii++)
#pragma unroll
                for (int cc = 0; cc < 4; cc++)
                    acc2[ii][cc] = fmaf(aa[ii], vv[cc], acc2[ii][cc]);
        }

        float inv[4];
#pragma unroll
        for (int ii = 0; ii < 4; ii++) inv[ii] = sm[SM_INV + oi0 + ii];

        __syncthreads();   // all simT reads done; reuse head as Ot[c][65]
#pragma unroll
        for (int cc = 0; cc < 4; cc++)
#pragma unroll
            for (int ii = 0; ii < 4; ii++)
                sm[(oc0 + cc) * 65 + oi0 + ii] = acc2[ii][cc] * inv[ii];
        __syncthreads();

        for (int idx = tid; idx < NPOS * D; idx += 256) {
            int c = idx >> 6, pos = idx & 63;
            int y = y0 + (pos >> 3), x = x0 + (pos & 7);
            out[base + (long)c * HW + y * IMG + x] = sm[c * 65 + pos];
        }
    }
}

// ---------------------------------------------------------------------------
extern "C" void kernel_launch(void* const* d_in, const int* in_sizes, int n_in,
                              void* d_out, int out_size)
{
    const float* noisy = (const float*)d_in[0];
    const float* aux   = (const float*)d_in[1];
    const float* w_map = (const float*)d_in[2];
    const float* b_map = (const float*)d_in[3];
    const float* w_q   = (const float*)d_in[4];
    const float* w_k   = (const float*)d_in[5];
    const float* w_v   = (const float*)d_in[6];
    const float* rel_h = (const float*)d_in[7];
    const float* rel_w = (const float*)d_in[8];
    float* out = (float*)d_out;

    float *naux, *q, *k, *v;
    cudaGetSymbolAddress((void**)&naux, g_naux);
    cudaGetSymbolAddress((void**)&q,    g_q);
    cudaGetSymbolAddress((void**)&k,    g_k);
    cudaGetSymbolAddress((void**)&v,    g_v);

    dim3 ggrid(HW / 128, CH / 128, BATCH);

    gemm_conv<<<ggrid, 256>>>(w_map, noisy, aux, 2 * CH, CH, naux, b_map, 1.f, 0);
    gemm_conv<<<ggrid, 256>>>(w_q, naux, nullptr, CH, CH, q, nullptr, 0.125f, 1);
    gemm_conv<<<ggrid, 256>>>(w_k, naux, nullptr, CH, CH, k, nullptr, 1.f, 2);
    gemm_conv<<<ggrid, 256>>>(w_v, noisy, nullptr, CH, CH, v, nullptr, 1.f, 2);

    size_t smem = (size_t)SM_TOT * sizeof(float);   // 106,048 B
    static bool attr_set = false;
    cudaFuncSetAttribute(attn_kernel,
                         cudaFuncAttributeMaxDynamicSharedMemorySize, (int)smem);
    (void)attr_set;
    attn_kernel<<<dim3(NB * NB, HEADS, BATCH), 256, smem>>>(q, k, v, rel_h, rel_w, out);
}

// round 3
// speedup vs baseline: 1.4387x; 1.1303x over previous
#include <cuda_runtime.h>
#include <cuda_bf16.h>

#define CH   256
#define IMG  128
#define HW   (IMG*IMG)
#define BATCH 4
#define HEADS 4
#define D    64
#define BLK  8
#define HALO 3
#define WIN  14
#define NB   16
#define NPOS 64
#define NWIN 196

__device__ float g_naux[(long)BATCH*CH*HW];
__device__ float g_q   [(long)BATCH*CH*HW];
__device__ float g_k   [(long)BATCH*CH*HW];
__device__ float g_v   [(long)BATCH*CH*HW];

// ---------------------------------------------------------------------------
// Conv1x1 GEMM, double-buffered smem, one barrier per k-tile.
// ---------------------------------------------------------------------------
__global__ __launch_bounds__(256, 2)
void gemm_conv(const float* __restrict__ A,
               const float* __restrict__ B0,
               const float* __restrict__ B1,
               int K, int K0,
               float* __restrict__ C,
               const float* __restrict__ bias,
               float scale, int mode)
{
    const int tid = threadIdx.x;
    const int b   = blockIdx.z;
    const int n0  = blockIdx.x * 128;
    const int m0  = blockIdx.y * 128;
    const long boff = (long)b * CH * HW;
    const float* Bb0 = B0 + boff;
    const float* Bb1 = B1 ? (B1 + boff) : nullptr;
    float* Cb = C + boff;

    __shared__ float As[2][16][132];
    __shared__ float Bs[2][16][128];

    const int ty8 = (tid >> 4) * 8;
    const int tx8 = (tid & 15) * 8;

    // load-index precompute
    const int arow0 = tid >> 2;          // +0 / +64
    const int acol  = (tid & 3) * 4;
    const int brow0 = tid >> 5;          // +0 / +8
    const int bcol  = (tid & 31) * 4;

    float acc[8][8];
#pragma unroll
    for (int i = 0; i < 8; i++)
#pragma unroll
        for (int j = 0; j < 8; j++) acc[i][j] = 0.f;

    const int ntiles = K / 16;
    float4 ar[2], br[2];

    // prologue: tile 0
#pragma unroll
    for (int p = 0; p < 2; p++)
        ar[p] = *(const float4*)&A[(long)(m0 + p * 64 + arow0) * K + acol];
#pragma unroll
    for (int p = 0; p < 2; p++) {
        int kr = p * 8 + brow0;
        const float* src = (kr < K0) ? (Bb0 + (long)kr * HW)
                                     : (Bb1 + (long)(kr - K0) * HW);
        br[p] = *(const float4*)&src[n0 + bcol];
    }
#pragma unroll
    for (int p = 0; p < 2; p++) {
        int row = p * 64 + arow0;
        As[0][acol + 0][row] = ar[p].x;
        As[0][acol + 1][row] = ar[p].y;
        As[0][acol + 2][row] = ar[p].z;
        As[0][acol + 3][row] = ar[p].w;
    }
#pragma unroll
    for (int p = 0; p < 2; p++)
        *(float4*)&Bs[0][p * 8 + brow0][bcol] = br[p];
    __syncthreads();

    for (int kt = 0; kt < ntiles; kt++) {
        const int cur = kt & 1, nxt = cur ^ 1;
        if (kt + 1 < ntiles) {
            int kb = (kt + 1) * 16;
#pragma unroll
            for (int p = 0; p < 2; p++)
                ar[p] = *(const float4*)&A[(long)(m0 + p * 64 + arow0) * K + kb + acol];
#pragma unroll
            for (int p = 0; p < 2; p++) {
                int kr = kb + p * 8 + brow0;
                const float* src = (kr < K0) ? (Bb0 + (long)kr * HW)
                                             : (Bb1 + (long)(kr - K0) * HW);
                br[p] = *(const float4*)&src[n0 + bcol];
            }
        }
#pragma unroll
        for (int kk = 0; kk < 16; kk++) {
            float a[8], bb[8];
#pragma unroll
            for (int i = 0; i < 8; i++) a[i] = As[cur][kk][ty8 + i];
#pragma unroll
            for (int j = 0; j < 8; j++) bb[j] = Bs[cur][kk][tx8 + j];
#pragma unroll
            for (int i = 0; i < 8; i++)
#pragma unroll
                for (int j = 0; j < 8; j++) acc[i][j] = fmaf(a[i], bb[j], acc[i][j]);
        }
        if (kt + 1 < ntiles) {
#pragma unroll
            for (int p = 0; p < 2; p++) {
                int row = p * 64 + arow0;
                As[nxt][acol + 0][row] = ar[p].x;
                As[nxt][acol + 1][row] = ar[p].y;
                As[nxt][acol + 2][row] = ar[p].z;
                As[nxt][acol + 3][row] = ar[p].w;
            }
#pragma unroll
            for (int p = 0; p < 2; p++)
                *(float4*)&Bs[nxt][p * 8 + brow0][bcol] = br[p];
            __syncthreads();
        }
    }

#pragma unroll
    for (int i = 0; i < 8; i++) {
        int o = m0 + ty8 + i;
        float bi = (mode == 0) ? bias[o] : 0.f;
        float* dst = &Cb[(long)o * HW + n0 + tx8];
#pragma unroll
        for (int j = 0; j < 8; j++) {
            float v = acc[i][j];
            if (mode == 0)      v = fmaxf(v + bi, 0.f);
            else if (mode == 1) v = v * scale;
            dst[j] = v;
        }
    }
}

// ---------------------------------------------------------------------------
// Halo attention v3: per-j threads for K/V loads (index math once per j),
// offset table reused for V; same overlay layout as v2.
// ---------------------------------------------------------------------------
#define SM_QC    0
#define SM_KC    4096
#define SM_SIMT  0
#define SM_VR    12800
#define VR_STR   68
#define SM_RED   26128
#define SM_MX    26384
#define SM_INV   26448
#define SM_JT    26512
#define SM_TOT   26712

__global__ __launch_bounds__(256, 2)
void attn_kernel(const float* __restrict__ gq, const float* __restrict__ gk,
                 const float* __restrict__ gv, const float* __restrict__ relh,
                 const float* __restrict__ relw, float* __restrict__ out)
{
    extern __shared__ float sm[];
    int* jtab = (int*)&sm[SM_JT];

    const int tid = threadIdx.x;
    const int blk = blockIdx.x;
    const int h   = blockIdx.y;
    const int b   = blockIdx.z;
    const int by  = blk >> 4, bx = blk & 15;
    const int y0  = by * BLK, x0 = bx * BLK;
    const long base = ((long)b * CH + h * D) * HW;

    // ---- phase 1: K window (threads 0..199, one j each) + Q (threads 200+) --
    if (tid < 200) {
        const int j = tid;
        const bool pad = j >= NWIN;
        const int iw = j / WIN, jw = j - iw * WIN;
        const int y = y0 - HALO + iw, x = x0 - HALO + jw;
        const bool valid = !pad && ((unsigned)y < IMG) && ((unsigned)x < IMG);
        const int off = valid ? y * IMG + x : 0;
        jtab[j] = valid ? off : -1;
        if (!pad) {
            const float* gkb = gk + base + off;
            const float* rh  = relh + iw * 32;
            const float* rw  = relw + jw * 32;
#pragma unroll 8
            for (int c = 0; c < 32; c++) {
                float v = valid ? __ldg(&gkb[c * HW]) : 0.f;
                sm[SM_KC + c * 200 + j] = v + rh[c];
            }
#pragma unroll 8
            for (int c = 32; c < 64; c++) {
                float v = valid ? __ldg(&gkb[c * HW]) : 0.f;
                sm[SM_KC + c * 200 + j] = v + rw[c - 32];
            }
        } else {
#pragma unroll 8
            for (int c = 0; c < 64; c++) sm[SM_KC + c * 200 + j] = 0.f;
        }
    } else {
        for (int idx = tid - 200; idx < NPOS * D; idx += 56) {
            int c = idx >> 6, pos = idx & 63;
            int y = y0 + (pos >> 3), x = x0 + (pos & 7);
            sm[SM_QC + c * 64 + pos] = gq[base + (long)c * HW + y * IMG + x];
        }
    }
    __syncthreads();

    // ---- phase 2: simT[j][i] = sum_c K[j][c]*Q[i][c] (8x8 tiles, 200 thr) ---
    float acc[8][8];
    int j0 = 0, i0 = 0;
    if (tid < 200) {
        j0 = (tid >> 3) * 8;
        i0 = (tid & 7) * 8;
#pragma unroll
        for (int a = 0; a < 8; a++)
#pragma unroll
            for (int bb2 = 0; bb2 < 8; bb2++) acc[a][bb2] = 0.f;

#pragma unroll 2
        for (int c = 0; c < D; c++) {
            float4 k0v = *(const float4*)&sm[SM_KC + c * 200 + j0];
            float4 k1v = *(const float4*)&sm[SM_KC + c * 200 + j0 + 4];
            float4 q0v = *(const float4*)&sm[SM_QC + c * 64 + i0];
            float4 q1v = *(const float4*)&sm[SM_QC + c * 64 + i0 + 4];
            float ka[8] = {k0v.x,k0v.y,k0v.z,k0v.w,k1v.x,k1v.y,k1v.z,k1v.w};
            float qa[8] = {q0v.x,q0v.y,q0v.z,q0v.w,q1v.x,q1v.y,q1v.z,q1v.w};
#pragma unroll
            for (int jj = 0; jj < 8; jj++)
#pragma unroll
                for (int ii = 0; ii < 8; ii++)
                    acc[jj][ii] = fmaf(ka[jj], qa[ii], acc[jj][ii]);
        }
    }
    __syncthreads();   // Qc/Kc dead

    // ---- phase 3: write simT; load V via offset table -----------------------
    if (tid < 200) {
#pragma unroll
        for (int jj = 0; jj < 8; jj++) {
            *(float4*)&sm[SM_SIMT + (j0 + jj) * 64 + i0]     =
                make_float4(acc[jj][0], acc[jj][1], acc[jj][2], acc[jj][3]);
            *(float4*)&sm[SM_SIMT + (j0 + jj) * 64 + i0 + 4] =
                make_float4(acc[jj][4], acc[jj][5], acc[jj][6], acc[jj][7]);
        }
    }
    if (tid < NWIN) {
        const int j = tid;
        const int off = jtab[j];
        const bool valid = off >= 0;
        const float* gvb = gv + base + (valid ? off : 0);
#pragma unroll 8
        for (int c = 0; c < 64; c++)
            sm[SM_VR + j * VR_STR + c] = valid ? __ldg(&gvb[c * HW]) : 0.f;
    }
    __syncthreads();

    // ---- phase 4: softmax over j per column i -------------------------------
    {
        const int i = tid & 63, p = tid >> 6;
        const int jb = p * 49;
        float m = -1e30f;
#pragma unroll 7
        for (int jj = 0; jj < 49; jj++)
            m = fmaxf(m, sm[SM_SIMT + (jb + jj) * 64 + i]);
        sm[SM_RED + p * 64 + i] = m;
        __syncthreads();
        if (tid < 64) {
            float mm = fmaxf(fmaxf(sm[SM_RED + tid], sm[SM_RED + 64 + tid]),
                             fmaxf(sm[SM_RED + 128 + tid], sm[SM_RED + 192 + tid]));
            sm[SM_MX + tid] = mm;
        }
        __syncthreads();
        float mm = sm[SM_MX + i];
        float s = 0.f;
#pragma unroll 7
        for (int jj = 0; jj < 49; jj++) {
            float e = __expf(sm[SM_SIMT + (jb + jj) * 64 + i] - mm);
            sm[SM_SIMT + (jb + jj) * 64 + i] = e;
            s += e;
        }
        sm[SM_RED + p * 64 + i] = s;
        __syncthreads();
        if (tid < 64) {
            float ss = sm[SM_RED + tid] + sm[SM_RED + 64 + tid]
                     + sm[SM_RED + 128 + tid] + sm[SM_RED + 192 + tid];
            sm[SM_INV + tid] = 1.f / ss;
        }
        __syncthreads();
    }

    // ---- phase 5: out = softmax @ V -----------------------------------------
    {
        const int it = tid >> 4, ct = tid & 15;
        const int oi0 = it * 4, oc0 = ct * 4;
        float acc2[4][4];
#pragma unroll
        for (int a = 0; a < 4; a++)
#pragma unroll
            for (int bb2 = 0; bb2 < 4; bb2++) acc2[a][bb2] = 0.f;

#pragma unroll 4
        for (int j = 0; j < NWIN; j++) {
            float4 av = *(const float4*)&sm[SM_SIMT + j * 64 + oi0];
            float4 bv = *(const float4*)&sm[SM_VR + j * VR_STR + oc0];
            float aa[4] = {av.x, av.y, av.z, av.w};
            float vv[4] = {bv.x, bv.y, bv.z, bv.w};
#pragma unroll
            for (int ii = 0; ii < 4; ii++)
#pragma unroll
                for (int cc = 0; cc < 4; cc++)
                    acc2[ii][cc] = fmaf(aa[ii], vv[cc], acc2[ii][cc]);
        }

        float inv[4];
#pragma unroll
        for (int ii = 0; ii < 4; ii++) inv[ii] = sm[SM_INV + oi0 + ii];

        __syncthreads();
#pragma unroll
        for (int cc = 0; cc < 4; cc++)
#pragma unroll
            for (int ii = 0; ii < 4; ii++)
                sm[(oc0 + cc) * 65 + oi0 + ii] = acc2[ii][cc] * inv[ii];
        __syncthreads();

        for (int idx = tid; idx < NPOS * D; idx += 256) {
            int c = idx >> 6, pos = idx & 63;
            int y = y0 + (pos >> 3), x = x0 + (pos & 7);
            out[base + (long)c * HW + y * IMG + x] = sm[c * 65 + pos];
        }
    }
}

// no-op spacer so attention is the 6th launch (ncu -s 5 -c 1 captures it)
__global__ void noop_kernel() {}

// ---------------------------------------------------------------------------
extern "C" void kernel_launch(void* const* d_in, const int* in_sizes, int n_in,
                              void* d_out, int out_size)
{
    const float* noisy = (const float*)d_in[0];
    const float* aux   = (const float*)d_in[1];
    const float* w_map = (const float*)d_in[2];
    const float* b_map = (const float*)d_in[3];
    const float* w_q   = (const float*)d_in[4];
    const float* w_k   = (const float*)d_in[5];
    const float* w_v   = (const float*)d_in[6];
    const float* rel_h = (const float*)d_in[7];
    const float* rel_w = (const float*)d_in[8];
    float* out = (float*)d_out;

    float *naux, *q, *k, *v;
    cudaGetSymbolAddress((void**)&naux, g_naux);
    cudaGetSymbolAddress((void**)&q,    g_q);
    cudaGetSymbolAddress((void**)&k,    g_k);
    cudaGetSymbolAddress((void**)&v,    g_v);

    dim3 ggrid(HW / 128, CH / 128, BATCH);

    gemm_conv<<<ggrid, 256>>>(w_map, noisy, aux, 2 * CH, CH, naux, b_map, 1.f, 0);
    gemm_conv<<<ggrid, 256>>>(w_q, naux, nullptr, CH, CH, q, nullptr, 0.125f, 1);
    gemm_conv<<<ggrid, 256>>>(w_k, naux, nullptr, CH, CH, k, nullptr, 1.f, 2);
    gemm_conv<<<ggrid, 256>>>(w_v, noisy, nullptr, CH, CH, v, nullptr, 1.f, 2);

    noop_kernel<<<1, 32>>>();

    size_t smem = (size_t)SM_TOT * sizeof(float);
    cudaFuncSetAttribute(attn_kernel,
                         cudaFuncAttributeMaxDynamicSharedMemorySize, (int)smem);
    attn_kernel<<<dim3(NB * NB, HEADS, BATCH), 256, smem>>>(q, k, v, rel_h, rel_w, out);
}

// round 4
// speedup vs baseline: 1.7133x; 1.1909x over previous
#include <cuda_runtime.h>

#define CH   256
#define IMG  128
#define HW   (IMG*IMG)
#define BATCH 4
#define HEADS 4
#define D    64
#define BLK  8
#define HALO 3
#define WIN  14
#define NB   16
#define NPOS 64
#define NWIN 196

typedef unsigned long long ull;

__device__ __forceinline__ ull pack2(float lo, float hi) {
    ull r; asm("mov.b64 %0, {%1,%2};" : "=l"(r) : "f"(lo), "f"(hi)); return r;
}
__device__ __forceinline__ ull pack2b(float v) { return pack2(v, v); }
__device__ __forceinline__ void fma2(ull& d, ull a, ull b) {
    asm("fma.rn.f32x2 %0, %1, %2, %0;" : "+l"(d) : "l"(a), "l"(b));
}
__device__ __forceinline__ void unpack2(ull v, float& lo, float& hi) {
    asm("mov.b64 {%0,%1}, %2;" : "=f"(lo), "=f"(hi) : "l"(v));
}

// Scratch. g_k/g_v have 16-float pads front+back: attention loads aligned
// float4 windows starting at x0-4, which can under/overrun by <=16 floats.
__device__ float g_naux[(long)BATCH*CH*HW];
__device__ float g_q   [(long)BATCH*CH*HW];
__device__ float g_k   [(long)BATCH*CH*HW + 32];
__device__ float g_v   [(long)BATCH*CH*HW + 32];

// ---------------------------------------------------------------------------
// Conv1x1 GEMM, double-buffered, f32x2 packed FMA inner loop.
// ---------------------------------------------------------------------------
__global__ __launch_bounds__(256, 2)
void gemm_conv(const float* __restrict__ A,
               const float* __restrict__ B0,
               const float* __restrict__ B1,
               int K, int K0,
               float* __restrict__ C,
               const float* __restrict__ bias,
               float scale, int mode)
{
    const int tid = threadIdx.x;
    const int b   = blockIdx.z;
    const int n0  = blockIdx.x * 128;
    const int m0  = blockIdx.y * 128;
    const long boff = (long)b * CH * HW;
    const float* Bb0 = B0 + boff;
    const float* Bb1 = B1 ? (B1 + boff) : nullptr;
    float* Cb = C + boff;

    __shared__ float As[2][16][132];
    __shared__ float Bs[2][16][128];

    const int ty8 = (tid >> 4) * 8;
    const int tx8 = (tid & 15) * 8;

    const int arow0 = tid >> 2;
    const int acol  = (tid & 3) * 4;
    const int brow0 = tid >> 5;
    const int bcol  = (tid & 31) * 4;

    ull acc[8][4];
#pragma unroll
    for (int i = 0; i < 8; i++)
#pragma unroll
        for (int q = 0; q < 4; q++) acc[i][q] = 0ull;

    const int ntiles = K / 16;
    float4 ar[2], br[2];

#pragma unroll
    for (int p = 0; p < 2; p++)
        ar[p] = *(const float4*)&A[(long)(m0 + p * 64 + arow0) * K + acol];
#pragma unroll
    for (int p = 0; p < 2; p++) {
        int kr = p * 8 + brow0;
        const float* src = (kr < K0) ? (Bb0 + (long)kr * HW)
                                     : (Bb1 + (long)(kr - K0) * HW);
        br[p] = *(const float4*)&src[n0 + bcol];
    }
#pragma unroll
    for (int p = 0; p < 2; p++) {
        int row = p * 64 + arow0;
        As[0][acol + 0][row] = ar[p].x;
        As[0][acol + 1][row] = ar[p].y;
        As[0][acol + 2][row] = ar[p].z;
        As[0][acol + 3][row] = ar[p].w;
    }
#pragma unroll
    for (int p = 0; p < 2; p++)
        *(float4*)&Bs[0][p * 8 + brow0][bcol] = br[p];
    __syncthreads();

    for (int kt = 0; kt < ntiles; kt++) {
        const int cur = kt & 1, nxt = cur ^ 1;
        if (kt + 1 < ntiles) {
            int kb = (kt + 1) * 16;
#pragma unroll
            for (int p = 0; p < 2; p++)
                ar[p] = *(const float4*)&A[(long)(m0 + p * 64 + arow0) * K + kb + acol];
#pragma unroll
            for (int p = 0; p < 2; p++) {
                int kr = kb + p * 8 + brow0;
                const float* src = (kr < K0) ? (Bb0 + (long)kr * HW)
                                             : (Bb1 + (long)(kr - K0) * HW);
                br[p] = *(const float4*)&src[n0 + bcol];
            }
        }
#pragma unroll
        for (int kk = 0; kk < 16; kk++) {
            float4 a0 = *(const float4*)&As[cur][kk][ty8];
            float4 a1 = *(const float4*)&As[cur][kk][ty8 + 4];
            float4 b0 = *(const float4*)&Bs[cur][kk][tx8];
            float4 b1 = *(const float4*)&Bs[cur][kk][tx8 + 4];
            float a[8] = {a0.x,a0.y,a0.z,a0.w,a1.x,a1.y,a1.z,a1.w};
            ull b2[4] = {pack2(b0.x,b0.y), pack2(b0.z,b0.w),
                         pack2(b1.x,b1.y), pack2(b1.z,b1.w)};
#pragma unroll
            for (int i = 0; i < 8; i++) {
                ull ai = pack2b(a[i]);
#pragma unroll
                for (int q = 0; q < 4; q++) fma2(acc[i][q], ai, b2[q]);
            }
        }
        if (kt + 1 < ntiles) {
#pragma unroll
            for (int p = 0; p < 2; p++) {
                int row = p * 64 + arow0;
                As[nxt][acol + 0][row] = ar[p].x;
                As[nxt][acol + 1][row] = ar[p].y;
                As[nxt][acol + 2][row] = ar[p].z;
                As[nxt][acol + 3][row] = ar[p].w;
            }
#pragma unroll
            for (int p = 0; p < 2; p++)
                *(float4*)&Bs[nxt][p * 8 + brow0][bcol] = br[p];
            __syncthreads();
        }
    }

#pragma unroll
    for (int i = 0; i < 8; i++) {
        int o = m0 + ty8 + i;
        float bi = (mode == 0) ? bias[o] : 0.f;
        float c[8];
#pragma unroll
        for (int q = 0; q < 4; q++) unpack2(acc[i][q], c[2*q], c[2*q+1]);
#pragma unroll
        for (int j = 0; j < 8; j++) {
            if (mode == 0)      c[j] = fmaxf(c[j] + bi, 0.f);
            else if (mode == 1) c[j] = c[j] * scale;
        }
        float* dst = &Cb[(long)o * HW + n0 + tx8];
        *(float4*)&dst[0] = make_float4(c[0], c[1], c[2], c[3]);
        *(float4*)&dst[4] = make_float4(c[4], c[5], c[6], c[7]);
    }
}

// ---------------------------------------------------------------------------
// Halo attention v4: vectorized window loads, f32x2 matmuls, j-split AV.
// ---------------------------------------------------------------------------
#define SM_QC    0
#define SM_KC    4096
#define SM_SIMT  0
#define SM_VR    12800
#define VR_STR   68
#define SM_RED   26128
#define SM_MX    26384
#define SM_INV   26448
#define SM_REL   26512
#define SM_TOT   27408    // floats (109,632 B)

__global__ __launch_bounds__(256, 2)
void attn_kernel(const float* __restrict__ gq, const float* __restrict__ gk,
                 const float* __restrict__ gv, const float* __restrict__ relh,
                 const float* __restrict__ relw, float* __restrict__ out)
{
    extern __shared__ float sm[];
    const int tid = threadIdx.x;
    const int blk = blockIdx.x;
    const int h   = blockIdx.y;
    const int b   = blockIdx.z;
    const int by  = blk >> 4, bx = blk & 15;
    const int y0  = by * BLK, x0 = bx * BLK;
    const long base = ((long)b * CH + h * D) * HW;

    // ---- phase 0: preload rel tables (relw transposed) ----------------------
    for (int t = tid; t < 896; t += 256) {
        if (t < 448) sm[SM_REL + t] = relh[t];
        else {
            int m = t - 448, jw = m >> 5, cc = m & 31;
            sm[SM_REL + 448 + cc * 14 + jw] = relw[m];
        }
    }
    __syncthreads();

    // ---- phase 1: Q (vec) + K window (vec, bias, pad) ------------------------
    if (tid < 64) {
        float* kr = &sm[SM_KC + tid * 200];
        kr[196] = 0.f; kr[197] = 0.f; kr[198] = 0.f; kr[199] = 0.f;
    }
    for (int t = tid; t < 1408; t += 256) {
        if (t < 512) {
            int c = t >> 3, r = t & 7;
            const float* src = gq + base + (long)c * HW + (y0 + r) * IMG + x0;
            float4 qa = *(const float4*)src;
            float4 qb = *(const float4*)(src + 4);
            *(float4*)&sm[SM_QC + c * 64 + r * 8]     = qa;
            *(float4*)&sm[SM_QC + c * 64 + r * 8 + 4] = qb;
        } else {
            int tk = t - 512;
            int c = tk / 14, iw = tk - c * 14;
            int y = y0 - HALO + iw;
            float w[16];
            if ((unsigned)y < IMG) {
                const float* src = gk + base + (long)c * HW + y * IMG + x0 - 4;
                float4 f0 = *(const float4*)src;
                float4 f1 = *(const float4*)(src + 4);
                float4 f2 = *(const float4*)(src + 8);
                float4 f3 = *(const float4*)(src + 12);
                w[0]=f0.x; w[1]=f0.y; w[2]=f0.z; w[3]=f0.w;
                w[4]=f1.x; w[5]=f1.y; w[6]=f1.z; w[7]=f1.w;
                w[8]=f2.x; w[9]=f2.y; w[10]=f2.z; w[11]=f2.w;
                w[12]=f3.x; w[13]=f3.y; w[14]=f3.z; w[15]=f3.w;
                if (x0 == 0)   { w[1]=0.f; w[2]=0.f; w[3]=0.f; }
                if (x0 == 120) { w[12]=0.f; w[13]=0.f; w[14]=0.f; }
            } else {
#pragma unroll
                for (int m = 0; m < 16; m++) w[m] = 0.f;
            }
            float* dst = &sm[SM_KC + c * 200 + iw * 14];
            if (c < 32) {
                float bh = sm[SM_REL + iw * 32 + c];
#pragma unroll
                for (int jw = 0; jw < 14; jw++) dst[jw] = w[jw + 1] + bh;
            } else {
                const float* rw = &sm[SM_REL + 448 + (c - 32) * 14];
#pragma unroll
                for (int jw = 0; jw < 14; jw++) dst[jw] = w[jw + 1] + rw[jw];
            }
        }
    }
    __syncthreads();

    // ---- phase 2: simT[j][i] = K @ Q^T, 8x8 tiles, f32x2 ---------------------
    ull acc[8][4];
    int j0 = 0, i0 = 0;
    if (tid < 200) {
        j0 = (tid >> 3) * 8;
        i0 = (tid & 7) * 8;
#pragma unroll
        for (int a = 0; a < 8; a++)
#pragma unroll
            for (int q = 0; q < 4; q++) acc[a][q] = 0ull;

        for (int c = 0; c < D; c++) {
            float4 k0 = *(const float4*)&sm[SM_KC + c * 200 + j0];
            float4 k1 = *(const float4*)&sm[SM_KC + c * 200 + j0 + 4];
            float4 q0 = *(const float4*)&sm[SM_QC + c * 64 + i0];
            float4 q1 = *(const float4*)&sm[SM_QC + c * 64 + i0 + 4];
            float ka[8] = {k0.x,k0.y,k0.z,k0.w,k1.x,k1.y,k1.z,k1.w};
            ull q2[4] = {pack2(q0.x,q0.y), pack2(q0.z,q0.w),
                         pack2(q1.x,q1.y), pack2(q1.z,q1.w)};
#pragma unroll
            for (int jj = 0; jj < 8; jj++) {
                ull kb = pack2b(ka[jj]);
#pragma unroll
                for (int q = 0; q < 4; q++) fma2(acc[jj][q], kb, q2[q]);
            }
        }
    }
    __syncthreads();   // Qc/Kc dead

    // ---- phase 3: write simT; V window (vec, pad, transposed store) ----------
    if (tid < 200) {
#pragma unroll
        for (int jj = 0; jj < 8; jj++) {
            float c0,c1,c2,c3,c4,c5,c6,c7;
            unpack2(acc[jj][0], c0, c1);
            unpack2(acc[jj][1], c2, c3);
            unpack2(acc[jj][2], c4, c5);
            unpack2(acc[jj][3], c6, c7);
            *(float4*)&sm[SM_SIMT + (j0 + jj) * 64 + i0]     = make_float4(c0,c1,c2,c3);
            *(float4*)&sm[SM_SIMT + (j0 + jj) * 64 + i0 + 4] = make_float4(c4,c5,c6,c7);
        }
    }
    for (int t = tid; t < 896; t += 256) {
        int c = t / 14, iw = t - c * 14;
        int y = y0 - HALO + iw;
        float w[16];
        if ((unsigned)y < IMG) {
            const float* src = gv + base + (long)c * HW + y * IMG + x0 - 4;
            float4 f0 = *(const float4*)src;
            float4 f1 = *(const float4*)(src + 4);
            float4 f2 = *(const float4*)(src + 8);
            float4 f3 = *(const float4*)(src + 12);
            w[0]=f0.x; w[1]=f0.y; w[2]=f0.z; w[3]=f0.w;
            w[4]=f1.x; w[5]=f1.y; w[6]=f1.z; w[7]=f1.w;
            w[8]=f2.x; w[9]=f2.y; w[10]=f2.z; w[11]=f2.w;
            w[12]=f3.x; w[13]=f3.y; w[14]=f3.z; w[15]=f3.w;
            if (x0 == 0)   { w[1]=0.f; w[2]=0.f; w[3]=0.f; }
            if (x0 == 120) { w[12]=0.f; w[13]=0.f; w[14]=0.f; }
        } else {
#pragma unroll
            for (int m = 0; m < 16; m++) w[m] = 0.f;
        }
#pragma unroll
        for (int jw = 0; jw < 14; jw++)
            sm[SM_VR + (iw * 14 + jw) * VR_STR + c] = w[jw + 1];
    }
    __syncthreads();

    // ---- phase 4: softmax over j per column i (unnormalized) -----------------
    {
        const int i = tid & 63, p = tid >> 6;
        const int jb = p * 49;
        float m = -1e30f;
#pragma unroll 7
        for (int jj = 0; jj < 49; jj++)
            m = fmaxf(m, sm[SM_SIMT + (jb + jj) * 64 + i]);
        sm[SM_RED + p * 64 + i] = m;
        __syncthreads();
        if (tid < 64) {
            float mm = fmaxf(fmaxf(sm[SM_RED + tid], sm[SM_RED + 64 + tid]),
                             fmaxf(sm[SM_RED + 128 + tid], sm[SM_RED + 192 + tid]));
            sm[SM_MX + tid] = mm;
        }
        __syncthreads();
        float mm = sm[SM_MX + i];
        float s = 0.f;
#pragma unroll 7
        for (int jj = 0; jj < 49; jj++) {
            float e = __expf(sm[SM_SIMT + (jb + jj) * 64 + i] - mm);
            sm[SM_SIMT + (jb + jj) * 64 + i] = e;
            s += e;
        }
        sm[SM_RED + p * 64 + i] = s;
        __syncthreads();
        if (tid < 64) {
            float ss = sm[SM_RED + tid] + sm[SM_RED + 64 + tid]
                     + sm[SM_RED + 128 + tid] + sm[SM_RED + 192 + tid];
            sm[SM_INV + tid] = 1.f / ss;
        }
        __syncthreads();
    }

    // ---- phase 5: j-split AV, 8x8 f32x2 tiles + partial reduce ---------------
    {
        const int p   = tid >> 6;
        const int t64 = tid & 63;
        const int oi0 = (t64 >> 3) * 8, oc0 = (t64 & 7) * 8;
        ull acc2[8][4];
#pragma unroll
        for (int a = 0; a < 8; a++)
#pragma unroll
            for (int q = 0; q < 4; q++) acc2[a][q] = 0ull;

        const int jb = p * 49;
        for (int jj = 0; jj < 49; jj++) {
            const int j = jb + jj;
            float4 a0 = *(const float4*)&sm[SM_SIMT + j * 64 + oi0];
            float4 a1 = *(const float4*)&sm[SM_SIMT + j * 64 + oi0 + 4];
            float4 v0 = *(const float4*)&sm[SM_VR + j * VR_STR + oc0];
            float4 v1 = *(const float4*)&sm[SM_VR + j * VR_STR + oc0 + 4];
            float aa[8] = {a0.x,a0.y,a0.z,a0.w,a1.x,a1.y,a1.z,a1.w};
            ull v2[4] = {pack2(v0.x,v0.y), pack2(v0.z,v0.w),
                         pack2(v1.x,v1.y), pack2(v1.z,v1.w)};
#pragma unroll
            for (int ii = 0; ii < 8; ii++) {
                ull ab = pack2b(aa[ii]);
#pragma unroll
                for (int q = 0; q < 4; q++) fma2(acc2[ii][q], ab, v2[q]);
            }
        }
        __syncthreads();   // simT/VR dead; overlay partials

        float* pp = &sm[p * 4160];   // [64 pos][stride 65]
#pragma unroll
        for (int ii = 0; ii < 8; ii++) {
#pragma unroll
            for (int q = 0; q < 4; q++) {
                float lo, hi;
                unpack2(acc2[ii][q], lo, hi);
                pp[(oi0 + ii) * 65 + oc0 + 2 * q]     = lo;
                pp[(oi0 + ii) * 65 + oc0 + 2 * q + 1] = hi;
            }
        }
        __syncthreads();

        for (int idx = tid; idx < NPOS * D; idx += 256) {
            int pos = idx & 63, c = idx >> 6;
            float s = sm[pos * 65 + c] + sm[4160 + pos * 65 + c]
                    + sm[8320 + pos * 65 + c] + sm[12480 + pos * 65 + c];
            s *= sm[SM_INV + pos];
            out[base + (long)c * HW + (y0 + (pos >> 3)) * IMG + x0 + (pos & 7)] = s;
        }
    }
}

// ---------------------------------------------------------------------------
extern "C" void kernel_launch(void* const* d_in, const int* in_sizes, int n_in,
                              void* d_out, int out_size)
{
    const float* noisy = (const float*)d_in[0];
    const float* aux   = (const float*)d_in[1];
    const float* w_map = (const float*)d_in[2];
    const float* b_map = (const float*)d_in[3];
    const float* w_q   = (const float*)d_in[4];
    const float* w_k   = (const float*)d_in[5];
    const float* w_v   = (const float*)d_in[6];
    const float* rel_h = (const float*)d_in[7];
    const float* rel_w = (const float*)d_in[8];
    float* out = (float*)d_out;

    float *naux, *q, *kraw, *vraw;
    cudaGetSymbolAddress((void**)&naux, g_naux);
    cudaGetSymbolAddress((void**)&q,    g_q);
    cudaGetSymbolAddress((void**)&kraw, g_k);
    cudaGetSymbolAddress((void**)&vraw, g_v);
    float* k = kraw + 16;   // padded pointers
    float* v = vraw + 16;

    dim3 ggrid(HW / 128, CH / 128, BATCH);

    gemm_conv<<<ggrid, 256>>>(w_map, noisy, aux, 2 * CH, CH, naux, b_map, 1.f, 0);
    gemm_conv<<<ggrid, 256>>>(w_q, naux, nullptr, CH, CH, q, nullptr, 0.125f, 1);
    gemm_conv<<<ggrid, 256>>>(w_k, naux, nullptr, CH, CH, k, nullptr, 1.f, 2);
    gemm_conv<<<ggrid, 256>>>(w_v, noisy, nullptr, CH, CH, v, nullptr, 1.f, 2);

    size_t smem = (size_t)SM_TOT * sizeof(float);
    cudaFuncSetAttribute(attn_kernel,
                         cudaFuncAttributeMaxDynamicSharedMemorySize, (int)smem);
    attn_kernel<<<dim3(NB * NB, HEADS, BATCH), 256, smem>>>(q, k, v, rel_h, rel_w, out);
}

// round 5
// speedup vs baseline: 1.9210x; 1.1212x over previous
#include <cuda_runtime.h>
#include <cstdint>

#define CH   256
#define IMG  128
#define HW   (IMG*IMG)
#define BATCH 4
#define HEADS 4
#define D    64
#define BLK  8
#define HALO 3
#define WIN  14
#define NB   16
#define NPOS 64
#define NWIN 196

typedef unsigned long long ull;

__device__ __forceinline__ ull pack2(float lo, float hi) {
    ull r; asm("mov.b64 %0, {%1,%2};" : "=l"(r) : "f"(lo), "f"(hi)); return r;
}
__device__ __forceinline__ ull pack2b(float v) { return pack2(v, v); }
__device__ __forceinline__ void fma2(ull& d, ull a, ull b) {
    asm("fma.rn.f32x2 %0, %1, %2, %0;" : "+l"(d) : "l"(a), "l"(b));
}
__device__ __forceinline__ void unpack2(ull v, float& lo, float& hi) {
    asm("mov.b64 {%0,%1}, %2;" : "=f"(lo), "=f"(hi) : "l"(v));
}
__device__ __forceinline__ float tf32r(float x) {
    uint32_t r; asm("cvt.rna.tf32.f32 %0, %1;" : "=r"(r) : "f"(x));
    return __uint_as_float(r);
}
__device__ __forceinline__ void mma8(float* d, uint32_t a0, uint32_t a1,
                                     uint32_t a2, uint32_t a3,
                                     uint32_t b0, uint32_t b1) {
    asm("mma.sync.aligned.m16n8k8.row.col.f32.tf32.tf32.f32 "
        "{%0,%1,%2,%3},{%4,%5,%6,%7},{%8,%9},{%0,%1,%2,%3};"
        : "+f"(d[0]), "+f"(d[1]), "+f"(d[2]), "+f"(d[3])
        : "r"(a0), "r"(a1), "r"(a2), "r"(a3), "r"(b0), "r"(b1));
}

// Scratch; g_k/g_v padded 16 floats front+back for aligned halo float4 loads.
__device__ float g_naux[(long)BATCH*CH*HW];
__device__ float g_q   [(long)BATCH*CH*HW];
__device__ float g_k   [(long)BATCH*CH*HW + 32];
__device__ float g_v   [(long)BATCH*CH*HW + 32];

// ---------------------------------------------------------------------------
// Conv1x1 GEMM (f32x2, at packed-fp32 roofline) — unchanged from R4.
// ---------------------------------------------------------------------------
__global__ __launch_bounds__(256, 2)
void gemm_conv(const float* __restrict__ A,
               const float* __restrict__ B0,
               const float* __restrict__ B1,
               int K, int K0,
               float* __restrict__ C,
               const float* __restrict__ bias,
               float scale, int mode)
{
    const int tid = threadIdx.x;
    const int b   = blockIdx.z;
    const int n0  = blockIdx.x * 128;
    const int m0  = blockIdx.y * 128;
    const long boff = (long)b * CH * HW;
    const float* Bb0 = B0 + boff;
    const float* Bb1 = B1 ? (B1 + boff) : nullptr;
    float* Cb = C + boff;

    __shared__ float As[2][16][132];
    __shared__ float Bs[2][16][128];

    const int ty8 = (tid >> 4) * 8;
    const int tx8 = (tid & 15) * 8;
    const int arow0 = tid >> 2;
    const int acol  = (tid & 3) * 4;
    const int brow0 = tid >> 5;
    const int bcol  = (tid & 31) * 4;

    ull acc[8][4];
#pragma unroll
    for (int i = 0; i < 8; i++)
#pragma unroll
        for (int q = 0; q < 4; q++) acc[i][q] = 0ull;

    const int ntiles = K / 16;
    float4 ar[2], br[2];

#pragma unroll
    for (int p = 0; p < 2; p++)
        ar[p] = *(const float4*)&A[(long)(m0 + p * 64 + arow0) * K + acol];
#pragma unroll
    for (int p = 0; p < 2; p++) {
        int kr = p * 8 + brow0;
        const float* src = (kr < K0) ? (Bb0 + (long)kr * HW)
                                     : (Bb1 + (long)(kr - K0) * HW);
        br[p] = *(const float4*)&src[n0 + bcol];
    }
#pragma unroll
    for (int p = 0; p < 2; p++) {
        int row = p * 64 + arow0;
        As[0][acol + 0][row] = ar[p].x;
        As[0][acol + 1][row] = ar[p].y;
        As[0][acol + 2][row] = ar[p].z;
        As[0][acol + 3][row] = ar[p].w;
    }
#pragma unroll
    for (int p = 0; p < 2; p++)
        *(float4*)&Bs[0][p * 8 + brow0][bcol] = br[p];
    __syncthreads();

    for (int kt = 0; kt < ntiles; kt++) {
        const int cur = kt & 1, nxt = cur ^ 1;
        if (kt + 1 < ntiles) {
            int kb = (kt + 1) * 16;
#pragma unroll
            for (int p = 0; p < 2; p++)
                ar[p] = *(const float4*)&A[(long)(m0 + p * 64 + arow0) * K + kb + acol];
#pragma unroll
            for (int p = 0; p < 2; p++) {
                int kr = kb + p * 8 + brow0;
                const float* src = (kr < K0) ? (Bb0 + (long)kr * HW)
                                             : (Bb1 + (long)(kr - K0) * HW);
                br[p] = *(const float4*)&src[n0 + bcol];
            }
        }
#pragma unroll
        for (int kk = 0; kk < 16; kk++) {
            float4 a0 = *(const float4*)&As[cur][kk][ty8];
            float4 a1 = *(const float4*)&As[cur][kk][ty8 + 4];
            float4 b0 = *(const float4*)&Bs[cur][kk][tx8];
            float4 b1 = *(const float4*)&Bs[cur][kk][tx8 + 4];
            float a[8] = {a0.x,a0.y,a0.z,a0.w,a1.x,a1.y,a1.z,a1.w};
            ull b2[4] = {pack2(b0.x,b0.y), pack2(b0.z,b0.w),
                         pack2(b1.x,b1.y), pack2(b1.z,b1.w)};
#pragma unroll
            for (int i = 0; i < 8; i++) {
                ull ai = pack2b(a[i]);
#pragma unroll
                for (int q = 0; q < 4; q++) fma2(acc[i][q], ai, b2[q]);
            }
        }
        if (kt + 1 < ntiles) {
#pragma unroll
            for (int p = 0; p < 2; p++) {
                int row = p * 64 + arow0;
                As[nxt][acol + 0][row] = ar[p].x;
                As[nxt][acol + 1][row] = ar[p].y;
                As[nxt][acol + 2][row] = ar[p].z;
                As[nxt][acol + 3][row] = ar[p].w;
            }
#pragma unroll
            for (int p = 0; p < 2; p++)
                *(float4*)&Bs[nxt][p * 8 + brow0][bcol] = br[p];
            __syncthreads();
        }
    }

#pragma unroll
    for (int i = 0; i < 8; i++) {
        int o = m0 + ty8 + i;
        float bi = (mode == 0) ? bias[o] : 0.f;
        float c[8];
#pragma unroll
        for (int q = 0; q < 4; q++) unpack2(acc[i][q], c[2*q], c[2*q+1]);
#pragma unroll
        for (int j = 0; j < 8; j++) {
            if (mode == 0)      c[j] = fmaxf(c[j] + bi, 0.f);
            else if (mode == 1) c[j] = c[j] * scale;
        }
        float* dst = &Cb[(long)o * HW + n0 + tx8];
        *(float4*)&dst[0] = make_float4(c[0], c[1], c[2], c[3]);
        *(float4*)&dst[4] = make_float4(c[4], c[5], c[6], c[7]);
    }
}

// ---------------------------------------------------------------------------
// Halo attention v5: tf32 mma.sync for QK^T and AV.
// smem (floats):
//   Kw   @0      [208 j][stride 68]  (rows 196..207 zero)   -> later simT
//   Qc   @14144  [64 c][stride 72]                          -> later Vc
//   simT @0      [208 j][stride 68]
//   Vc   @14144  [64 c][stride 204]  (cols 196..199 zero)
//   rel  @27200 (896), red @28096 (256), mx @28352, inv @28416; TOT 28480
// ---------------------------------------------------------------------------
#define KW_OFF   0
#define KW_STR   68
#define QC_OFF   14144
#define QC_STR   72
#define ST_OFF   0
#define ST_STR   68
#define VC_OFF   14144
#define VC_STR   204
#define REL_OFF  27200
#define RED_OFF  28096
#define MX_OFF   28352
#define INV_OFF  28416
#define SM_TOT   28480

__global__ __launch_bounds__(256, 2)
void attn_kernel(const float* __restrict__ gq, const float* __restrict__ gk,
                 const float* __restrict__ gv, const float* __restrict__ relh,
                 const float* __restrict__ relw, float* __restrict__ out)
{
    extern __shared__ float sm[];
    const int tid  = threadIdx.x;
    const int lane = tid & 31, w = tid >> 5;
    const int gid  = lane >> 2, tig = lane & 3;
    const int blk = blockIdx.x;
    const int h   = blockIdx.y;
    const int b   = blockIdx.z;
    const int by  = blk >> 4, bx = blk & 15;
    const int y0  = by * BLK, x0 = bx * BLK;
    const long base = ((long)b * CH + h * D) * HW;

    // ---- phase 0: rel tables + zero Kw pad rows -----------------------------
    for (int t = tid; t < 896; t += 256) {
        if (t < 448) sm[REL_OFF + t] = relh[t];
        else {
            int m = t - 448, jw = m >> 5, cc = m & 31;
            sm[REL_OFF + 448 + cc * 14 + jw] = relw[m];
        }
    }
    for (int t = tid; t < 12 * KW_STR; t += 256)
        sm[KW_OFF + 196 * KW_STR + t] = 0.f;
    __syncthreads();

    // ---- phase 1: load Qc[c][i] and Kw[j][c] (+bias), tf32-rounded ----------
    for (int t = tid; t < 1408; t += 256) {
        if (t < 512) {
            int c = t >> 3, r = t & 7;
            const float* src = gq + base + (long)c * HW + (y0 + r) * IMG + x0;
            float4 qa = *(const float4*)src;
            float4 qb = *(const float4*)(src + 4);
            qa.x=tf32r(qa.x); qa.y=tf32r(qa.y); qa.z=tf32r(qa.z); qa.w=tf32r(qa.w);
            qb.x=tf32r(qb.x); qb.y=tf32r(qb.y); qb.z=tf32r(qb.z); qb.w=tf32r(qb.w);
            *(float4*)&sm[QC_OFF + c * QC_STR + r * 8]     = qa;
            *(float4*)&sm[QC_OFF + c * QC_STR + r * 8 + 4] = qb;
        } else {
            int tk = t - 512;
            int c = tk / 14, iw = tk - c * 14;
            int y = y0 - HALO + iw;
            float wv[16];
            if ((unsigned)y < IMG) {
                const float* src = gk + base + (long)c * HW + y * IMG + x0 - 4;
                float4 f0 = *(const float4*)src;
                float4 f1 = *(const float4*)(src + 4);
                float4 f2 = *(const float4*)(src + 8);
                float4 f3 = *(const float4*)(src + 12);
                wv[0]=f0.x; wv[1]=f0.y; wv[2]=f0.z; wv[3]=f0.w;
                wv[4]=f1.x; wv[5]=f1.y; wv[6]=f1.z; wv[7]=f1.w;
                wv[8]=f2.x; wv[9]=f2.y; wv[10]=f2.z; wv[11]=f2.w;
                wv[12]=f3.x; wv[13]=f3.y; wv[14]=f3.z; wv[15]=f3.w;
                if (x0 == 0)   { wv[1]=0.f; wv[2]=0.f; wv[3]=0.f; }
                if (x0 == 120) { wv[12]=0.f; wv[13]=0.f; wv[14]=0.f; }
            } else {
#pragma unroll
                for (int m = 0; m < 16; m++) wv[m] = 0.f;
            }
            if (c < 32) {
                float bh = sm[REL_OFF + iw * 32 + c];
#pragma unroll
                for (int jw = 0; jw < 14; jw++)
                    sm[KW_OFF + (iw * 14 + jw) * KW_STR + c] = tf32r(wv[jw + 1] + bh);
            } else {
                const float* rw = &sm[REL_OFF + 448 + (c - 32) * 14];
#pragma unroll
                for (int jw = 0; jw < 14; jw++)
                    sm[KW_OFF + (iw * 14 + jw) * KW_STR + c] = tf32r(wv[jw + 1] + rw[jw]);
            }
        }
    }
    __syncthreads();

    // ---- phase 2: simT[208 x 64] = Kw @ Qc  (tf32 mma) ----------------------
    // warp grid: wm = w>>2 (m-halves: 7 / 6 m16-tiles), wn = w&3 (2 n8-tiles)
    const int wm = w >> 2, wn = w & 3;
    const int nmt = 7 - wm;           // 7 or 6 m-tiles
    const int mbase = wm * 112;
    float Cf[7][2][4];
#pragma unroll
    for (int mt = 0; mt < 7; mt++)
#pragma unroll
        for (int nt = 0; nt < 2; nt++)
#pragma unroll
            for (int q = 0; q < 4; q++) Cf[mt][nt][q] = 0.f;

#pragma unroll
    for (int ks = 0; ks < 8; ks++) {
        const int c0 = ks * 8;
        uint32_t Bf[2][2];
#pragma unroll
        for (int nt = 0; nt < 2; nt++) {
            int n = wn * 16 + nt * 8 + gid;
            Bf[nt][0] = __float_as_uint(sm[QC_OFF + (c0 + tig)     * QC_STR + n]);
            Bf[nt][1] = __float_as_uint(sm[QC_OFF + (c0 + tig + 4) * QC_STR + n]);
        }
#pragma unroll
        for (int mt = 0; mt < 7; mt++) {
            if (mt < nmt) {
                int r = mbase + mt * 16 + gid;
                uint32_t a0 = __float_as_uint(sm[KW_OFF + r       * KW_STR + c0 + tig]);
                uint32_t a1 = __float_as_uint(sm[KW_OFF + (r + 8) * KW_STR + c0 + tig]);
                uint32_t a2 = __float_as_uint(sm[KW_OFF + r       * KW_STR + c0 + tig + 4]);
                uint32_t a3 = __float_as_uint(sm[KW_OFF + (r + 8) * KW_STR + c0 + tig + 4]);
                mma8(Cf[mt][0], a0, a1, a2, a3, Bf[0][0], Bf[0][1]);
                mma8(Cf[mt][1], a0, a1, a2, a3, Bf[1][0], Bf[1][1]);
            }
        }
    }
    __syncthreads();   // Kw, Qc dead

    // ---- phase 3: store simT frags; load Vc[c][j] (tf32) --------------------
#pragma unroll
    for (int mt = 0; mt < 7; mt++) {
        if (mt < nmt) {
#pragma unroll
            for (int nt = 0; nt < 2; nt++) {
                int r = mbase + mt * 16 + gid;
                int cidx = wn * 16 + nt * 8 + 2 * tig;
                *(float2*)&sm[ST_OFF + r * ST_STR + cidx] =
                    make_float2(Cf[mt][nt][0], Cf[mt][nt][1]);
                *(float2*)&sm[ST_OFF + (r + 8) * ST_STR + cidx] =
                    make_float2(Cf[mt][nt][2], Cf[mt][nt][3]);
            }
        }
    }
    for (int t = tid; t < 896; t += 256) {
        int c = t / 14, iw = t - c * 14;
        int y = y0 - HALO + iw;
        float wv[16];
        if ((unsigned)y < IMG) {
            const float* src = gv + base + (long)c * HW + y * IMG + x0 - 4;
            float4 f0 = *(const float4*)src;
            float4 f1 = *(const float4*)(src + 4);
            float4 f2 = *(const float4*)(src + 8);
            float4 f3 = *(const float4*)(src + 12);
            wv[0]=f0.x; wv[1]=f0.y; wv[2]=f0.z; wv[3]=f0.w;
            wv[4]=f1.x; wv[5]=f1.y; wv[6]=f1.z; wv[7]=f1.w;
            wv[8]=f2.x; wv[9]=f2.y; wv[10]=f2.z; wv[11]=f2.w;
            wv[12]=f3.x; wv[13]=f3.y; wv[14]=f3.z; wv[15]=f3.w;
            if (x0 == 0)   { wv[1]=0.f; wv[2]=0.f; wv[3]=0.f; }
            if (x0 == 120) { wv[12]=0.f; wv[13]=0.f; wv[14]=0.f; }
        } else {
#pragma unroll
            for (int m = 0; m < 16; m++) wv[m] = 0.f;
        }
        float* dst = &sm[VC_OFF + c * VC_STR + iw * 14];
#pragma unroll
        for (int jw = 0; jw < 14; jw++) dst[jw] = tf32r(wv[jw + 1]);
    }
    if (tid < 128) {  // zero Vc cols 196..199 (k-pad of AV)
        int c = tid >> 1, q = tid & 1;
        *(float2*)&sm[VC_OFF + c * VC_STR + 196 + 2 * q] = make_float2(0.f, 0.f);
    }
    __syncthreads();

    // ---- phase 4: softmax over j (cols of simT), zero pad rows --------------
    {
        const int i = tid & 63, p = tid >> 6;
        const int jb = p * 49;
        float m = -1e30f;
#pragma unroll 7
        for (int jj = 0; jj < 49; jj++)
            m = fmaxf(m, sm[ST_OFF + (jb + jj) * ST_STR + i]);
        sm[RED_OFF + p * 64 + i] = m;
        __syncthreads();
        if (tid < 64) {
            float mm = fmaxf(fmaxf(sm[RED_OFF + tid], sm[RED_OFF + 64 + tid]),
                             fmaxf(sm[RED_OFF + 128 + tid], sm[RED_OFF + 192 + tid]));
            sm[MX_OFF + tid] = mm;
        }
        __syncthreads();
        float mm = sm[MX_OFF + i];
        float s = 0.f;
#pragma unroll 7
        for (int jj = 0; jj < 49; jj++) {
            float e = __expf(sm[ST_OFF + (jb + jj) * ST_STR + i] - mm);
            s += e;
            sm[ST_OFF + (jb + jj) * ST_STR + i] = tf32r(e);
        }
        sm[RED_OFF + p * 64 + i] = s;
        // zero simT rows 196..199 (k-pad rows read by AV)
        if (tid < 4 * KW_STR) sm[ST_OFF + 196 * ST_STR + tid] = 0.f;
        __syncthreads();
        if (tid < 64) {
            float ss = sm[RED_OFF + tid] + sm[RED_OFF + 64 + tid]
                     + sm[RED_OFF + 128 + tid] + sm[RED_OFF + 192 + tid];
            sm[INV_OFF + tid] = 1.f / ss;
        }
        __syncthreads();
    }

    // ---- phase 5: outT[64c x 64i] = Vc @ simT (tf32 mma), scaled store ------
    {
        const int wm2 = w >> 1, wn2 = w & 1;
        const int cbase = wm2 * 16;
        float Df[4][4];
#pragma unroll
        for (int nt = 0; nt < 4; nt++)
#pragma unroll
            for (int q = 0; q < 4; q++) Df[nt][q] = 0.f;

        for (int kt = 0; kt < 25; kt++) {
            const int j0 = kt * 8;
            const int cr = cbase + gid;
            uint32_t a0 = __float_as_uint(sm[VC_OFF + cr       * VC_STR + j0 + tig]);
            uint32_t a1 = __float_as_uint(sm[VC_OFF + (cr + 8) * VC_STR + j0 + tig]);
            uint32_t a2 = __float_as_uint(sm[VC_OFF + cr       * VC_STR + j0 + tig + 4]);
            uint32_t a3 = __float_as_uint(sm[VC_OFF + (cr + 8) * VC_STR + j0 + tig + 4]);
#pragma unroll
            for (int nt = 0; nt < 4; nt++) {
                int n = wn2 * 32 + nt * 8 + gid;
                uint32_t b0 = __float_as_uint(sm[ST_OFF + (j0 + tig)     * ST_STR + n]);
                uint32_t b1 = __float_as_uint(sm[ST_OFF + (j0 + tig + 4) * ST_STR + n]);
                mma8(Df[nt], a0, a1, a2, a3, b0, b1);
            }
        }

#pragma unroll
        for (int nt = 0; nt < 4; nt++) {
            int i0 = wn2 * 32 + nt * 8 + 2 * tig;         // even, pair in-row
            float v0 = sm[INV_OFF + i0], v1 = sm[INV_OFF + i0 + 1];
            int row = (i0 >> 3), xc = i0 & 7;
            int c0 = cbase + gid;
            long o0 = base + (long)c0 * HW + (y0 + row) * IMG + x0 + xc;
            *(float2*)&out[o0] = make_float2(Df[nt][0] * v0, Df[nt][1] * v1);
            long o1 = o0 + (long)8 * HW;
            *(float2*)&out[o1] = make_float2(Df[nt][2] * v0, Df[nt][3] * v1);
        }
    }
}

// ---------------------------------------------------------------------------
extern "C" void kernel_launch(void* const* d_in, const int* in_sizes, int n_in,
                              void* d_out, int out_size)
{
    const float* noisy = (const float*)d_in[0];
    const float* aux   = (const float*)d_in[1];
    const float* w_map = (const float*)d_in[2];
    const float* b_map = (const float*)d_in[3];
    const float* w_q   = (const float*)d_in[4];
    const float* w_k   = (const float*)d_in[5];
    const float* w_v   = (const float*)d_in[6];
    const float* rel_h = (const float*)d_in[7];
    const float* rel_w = (const float*)d_in[8];
    float* out = (float*)d_out;

    float *naux, *q, *kraw, *vraw;
    cudaGetSymbolAddress((void**)&naux, g_naux);
    cudaGetSymbolAddress((void**)&q,    g_q);
    cudaGetSymbolAddress((void**)&kraw, g_k);
    cudaGetSymbolAddress((void**)&vraw, g_v);
    float* k = kraw + 16;
    float* v = vraw + 16;

    dim3 ggrid(HW / 128, CH / 128, BATCH);

    gemm_conv<<<ggrid, 256>>>(w_map, noisy, aux, 2 * CH, CH, naux, b_map, 1.f, 0);
    gemm_conv<<<ggrid, 256>>>(w_q, naux, nullptr, CH, CH, q, nullptr, 0.125f, 1);
    gemm_conv<<<ggrid, 256>>>(w_k, naux, nullptr, CH, CH, k, nullptr, 1.f, 2);
    gemm_conv<<<ggrid, 256>>>(w_v, noisy, nullptr, CH, CH, v, nullptr, 1.f, 2);

    size_t smem = (size_t)SM_TOT * sizeof(float);   // 113,920 B
    cudaFuncSetAttribute(attn_kernel,
                         cudaFuncAttributeMaxDynamicSharedMemorySize, (int)smem);
    attn_kernel<<<dim3(NB * NB, HEADS, BATCH), 256, smem>>>(q, k, v, rel_h, rel_w, out);
}